// round 8
// baseline (speedup 1.0000x reference)
#include <cuda_runtime.h>
#include <math.h>
#include <stdint.h>

#define Bsz 64
#define Ssz 256
#define Hsz 1024
#define BS  16384
#define NCTA 64

__device__ __align__(16) float g_Drw[(size_t)BS * 2048];
__device__ __align__(16) float g_Zp[8 * BS];
__device__ __align__(16) float g_G[BS];
__device__ __align__(256) unsigned g_hT[2][Hsz * Bsz];   // [k][b'] tf32 bits
__device__ unsigned g_ready[16];                          // cumulative per-chunk flags

#define PA 20
#define PB 132
#define SPW 34

__device__ __forceinline__ unsigned f2tf(float x) {
    unsigned r; asm("cvt.rna.tf32.f32 %0, %1;" : "=r"(r) : "f"(x)); return r;
}
__device__ __forceinline__ void mma8(float* c, const unsigned* a, const unsigned* b) {
    asm volatile("mma.sync.aligned.m16n8k8.row.col.f32.tf32.tf32.f32 "
                 "{%0,%1,%2,%3},{%4,%5,%6,%7},{%8,%9},{%0,%1,%2,%3};"
                 : "+f"(c[0]), "+f"(c[1]), "+f"(c[2]), "+f"(c[3])
                 : "r"(a[0]), "r"(a[1]), "r"(a[2]), "r"(a[3]), "r"(b[0]), "r"(b[1]));
}

__device__ __forceinline__ void tile_mma(const unsigned* sA, const unsigned* sB,
                                         float c[2][8][4], int lane, int wm, int wn) {
    const int q = lane >> 2, la3 = lane & 3;
#pragma unroll
    for (int kk = 0; kk < 16; kk += 8) {
        unsigned a[2][4];
#pragma unroll
        for (int mt = 0; mt < 2; mt++) {
            int r = wm * 32 + mt * 16 + q, cc = kk + la3;
            a[mt][0] = sA[r * PA + cc];     a[mt][1] = sA[(r + 8) * PA + cc];
            a[mt][2] = sA[r * PA + cc + 4]; a[mt][3] = sA[(r + 8) * PA + cc + 4];
        }
        int kx = kk + la3, cb = q * 16 + wn * 8;
        uint4 b0 = *(const uint4*)&sB[kx * PB + cb];
        uint4 b1 = *(const uint4*)&sB[kx * PB + cb + 4];
        uint4 b2 = *(const uint4*)&sB[(kx + 4) * PB + cb];
        uint4 b3 = *(const uint4*)&sB[(kx + 4) * PB + cb + 4];
        unsigned bf[8][2] = {{b0.x,b2.x},{b0.y,b2.y},{b0.z,b2.z},{b0.w,b2.w},
                             {b1.x,b3.x},{b1.y,b3.y},{b1.z,b3.z},{b1.w,b3.w}};
#pragma unroll
        for (int mt = 0; mt < 2; mt++)
#pragma unroll
            for (int nt = 0; nt < 8; nt++) mma8(c[mt][nt], a[mt], bf[nt]);
    }
}

__global__ void init_kernel() {
    int i = blockIdx.x * blockDim.x + threadIdx.x;
    if (i < 16) g_ready[i] = 0u;
    if (i < 2 * Bsz * Hsz) ((unsigned*)g_hT)[i] = 0u;
}

// ---------------- gate GEMM (double-buffered smem) ----------------
__global__ void __launch_bounds__(256) gate_kernel(
    const float* __restrict__ D, const float* __restrict__ Q, const float* __restrict__ PM,
    const float* __restrict__ W1, const float* __restrict__ b1, const float* __restrict__ W2)
{
    __shared__ __align__(16) unsigned sA[2 * 128 * PA];
    __shared__ __align__(16) unsigned sB[2 * 16 * PB];
    __shared__ float sRed[2][128];
    const int m0 = blockIdx.x * 128, n0 = blockIdx.y * 128;
    const int tid = threadIdx.x, lane = tid & 31, wid = tid >> 5, wm = wid & 3, wn = wid >> 2;
    float c[2][8][4];
#pragma unroll
    for (int i = 0; i < 2; i++)
#pragma unroll
        for (int j = 0; j < 8; j++)
#pragma unroll
            for (int k = 0; k < 4; k++) c[i][j][k] = 0.f;
    const int am = tid >> 1, ak = (tid & 1) * 8, bk = tid >> 4;
    float ra[8], rb[8];
    auto loadAB = [&](int k0) {
        const int qd = k0 >> 10, kk = (k0 & 1023) + ak;
        const int r = m0 + am, b = r >> 8;
        const float4* dp = (const float4*)(D + (size_t)r * Hsz + kk);
        const float4* op = (const float4*)((((qd & 1) == 0) ? Q : PM) + (size_t)b * Hsz + kk);
        float4 d0 = dp[0], d1 = dp[1], o0 = op[0], o1 = op[1];
        if (qd < 2) {
            ra[0] = d0.x * o0.x; ra[1] = d0.y * o0.y; ra[2] = d0.z * o0.z; ra[3] = d0.w * o0.w;
            ra[4] = d1.x * o1.x; ra[5] = d1.y * o1.y; ra[6] = d1.z * o1.z; ra[7] = d1.w * o1.w;
        } else {
            ra[0] = fabsf(d0.x - o0.x); ra[1] = fabsf(d0.y - o0.y); ra[2] = fabsf(d0.z - o0.z); ra[3] = fabsf(d0.w - o0.w);
            ra[4] = fabsf(d1.x - o1.x); ra[5] = fabsf(d1.y - o1.y); ra[6] = fabsf(d1.z - o1.z); ra[7] = fabsf(d1.w - o1.w);
        }
        const float4* wp = (const float4*)(W1 + (size_t)(k0 + bk) * Hsz + n0 + (tid & 15) * 8);
        float4 w0 = wp[0], w1 = wp[1];
        rb[0] = w0.x; rb[1] = w0.y; rb[2] = w0.z; rb[3] = w0.w;
        rb[4] = w1.x; rb[5] = w1.y; rb[6] = w1.z; rb[7] = w1.w;
    };
    auto storeAB = [&](int bsel) {
        unsigned* pA = sA + bsel * 128 * PA;
        unsigned* pB = sB + bsel * 16 * PB;
#pragma unroll
        for (int i = 0; i < 8; i++) pA[am * PA + ak + i] = f2tf(ra[i]);
#pragma unroll
        for (int i = 0; i < 8; i++) pB[bk * PB + i * 16 + (tid & 15)] = f2tf(rb[i]);
    };
    loadAB(0); storeAB(0); __syncthreads();
    int cur = 0;
    for (int k0 = 0; k0 < 4096; k0 += 16) {
        const bool more = (k0 + 16) < 4096;
        if (more) loadAB(k0 + 16);
        tile_mma(sA + cur * 128 * PA, sB + cur * 16 * PB, c, lane, wm, wn);
        if (more) storeAB(cur ^ 1);
        __syncthreads();
        cur ^= 1;
    }
#pragma unroll
    for (int mt = 0; mt < 2; mt++) {
        float s0 = 0.f, s1 = 0.f;
#pragma unroll
        for (int nt = 0; nt < 8; nt++) {
            int nc = n0 + wn * 64 + nt * 8 + (lane & 3) * 2;
            float bb0 = b1[nc], bb1 = b1[nc + 1];
            float w0 = W2[nc], w1 = W2[nc + 1];
            s0 += tanhf(c[mt][nt][0] + bb0) * w0 + tanhf(c[mt][nt][1] + bb1) * w1;
            s1 += tanhf(c[mt][nt][2] + bb0) * w0 + tanhf(c[mt][nt][3] + bb1) * w1;
        }
        s0 += __shfl_xor_sync(0xffffffffu, s0, 1); s0 += __shfl_xor_sync(0xffffffffu, s0, 2);
        s1 += __shfl_xor_sync(0xffffffffu, s1, 1); s1 += __shfl_xor_sync(0xffffffffu, s1, 2);
        if ((lane & 3) == 0) {
            int rl = wm * 32 + mt * 16 + (lane >> 2);
            sRed[wn][rl] = s0; sRed[wn][rl + 8] = s1;
        }
    }
    __syncthreads();
    if (tid < 128) g_Zp[blockIdx.y * BS + m0 + tid] = sRed[0][tid] + sRed[1][tid];
}

__global__ void __launch_bounds__(256) softmax_kernel() {
    __shared__ float red[256];
    const int b = blockIdx.x, s = threadIdx.x;
    float v = 0.f;
#pragma unroll
    for (int p = 0; p < 8; p++) v += g_Zp[p * BS + b * Ssz + s];
    red[s] = v; __syncthreads();
    for (int o = 128; o > 0; o >>= 1) { if (s < o) red[s] = fmaxf(red[s], red[s + o]); __syncthreads(); }
    float mx = red[0]; __syncthreads();
    float e = expf(v - mx);
    red[s] = e; __syncthreads();
    for (int o = 128; o > 0; o >>= 1) { if (s < o) red[s] += red[s + o]; __syncthreads(); }
    g_G[b * Ssz + s] = e / red[0];
}

// ---------------- Dr|Dw (double-buffered smem) ----------------
__global__ void __launch_bounds__(256) drw_kernel(
    const float* __restrict__ D, const float* __restrict__ Wr, const float* __restrict__ br,
    const float* __restrict__ Wx, const float* __restrict__ bx)
{
    __shared__ __align__(16) unsigned sA[2 * 128 * PA];
    __shared__ __align__(16) unsigned sB[2 * 16 * PB];
    const int m0 = blockIdx.x * 128, n0g = blockIdx.y * 128;
    const float* W = (n0g < 1024) ? Wr : Wx;
    const float* bias = (n0g < 1024) ? br : bx;
    const int n0 = n0g & 1023;
    const int tid = threadIdx.x, lane = tid & 31, wid = tid >> 5, wm = wid & 3, wn = wid >> 2;
    float c[2][8][4];
#pragma unroll
    for (int i = 0; i < 2; i++)
#pragma unroll
        for (int j = 0; j < 8; j++)
#pragma unroll
            for (int k = 0; k < 4; k++) c[i][j][k] = 0.f;
    const int am = tid >> 1, ak = (tid & 1) * 8, bk = tid >> 4;
    float ra[8], rb[8];
    auto loadAB = [&](int k0) {
        const float4* dp = (const float4*)(D + (size_t)(m0 + am) * Hsz + k0 + ak);
        float4 d0 = dp[0], d1 = dp[1];
        ra[0] = d0.x; ra[1] = d0.y; ra[2] = d0.z; ra[3] = d0.w;
        ra[4] = d1.x; ra[5] = d1.y; ra[6] = d1.z; ra[7] = d1.w;
        const float4* wp = (const float4*)(W + (size_t)(k0 + bk) * Hsz + n0 + (tid & 15) * 8);
        float4 w0 = wp[0], w1 = wp[1];
        rb[0] = w0.x; rb[1] = w0.y; rb[2] = w0.z; rb[3] = w0.w;
        rb[4] = w1.x; rb[5] = w1.y; rb[6] = w1.z; rb[7] = w1.w;
    };
    auto storeAB = [&](int bsel) {
        unsigned* pA = sA + bsel * 128 * PA;
        unsigned* pB = sB + bsel * 16 * PB;
#pragma unroll
        for (int i = 0; i < 8; i++) pA[am * PA + ak + i] = f2tf(ra[i]);
#pragma unroll
        for (int i = 0; i < 8; i++) pB[bk * PB + i * 16 + (tid & 15)] = f2tf(rb[i]);
    };
    loadAB(0); storeAB(0); __syncthreads();
    int cur = 0;
    for (int k0 = 0; k0 < 1024; k0 += 16) {
        const bool more = (k0 + 16) < 1024;
        if (more) loadAB(k0 + 16);
        tile_mma(sA + cur * 128 * PA, sB + cur * 16 * PB, c, lane, wm, wn);
        if (more) storeAB(cur ^ 1);
        __syncthreads();
        cur ^= 1;
    }
#pragma unroll
    for (int mt = 0; mt < 2; mt++)
#pragma unroll
        for (int nt = 0; nt < 8; nt++) {
            int nl = wn * 64 + nt * 8 + (lane & 3) * 2;
            int r0 = m0 + wm * 32 + mt * 16 + (lane >> 2);
            float bb0 = bias[n0 + nl], bb1 = bias[n0 + nl + 1];
            *(float2*)&g_Drw[(size_t)r0 * 2048 + n0g + nl] = make_float2(c[mt][nt][0] + bb0, c[mt][nt][1] + bb1);
            *(float2*)&g_Drw[(size_t)(r0 + 8) * 2048 + n0g + nl] = make_float2(c[mt][nt][2] + bb0, c[mt][nt][3] + bb1);
        }
}

// ---------------- persistent scan: per-chunk flags, no global barrier ----------------
#define SCAN_WORDS (16384 + 1024 * SPW + 64 * 33 + 32 + 8)
#define SCAN_SMEM  (SCAN_WORDS * 4)

__global__ void __launch_bounds__(256, 1) scan_kernel(
    const float* __restrict__ Ur, const float* __restrict__ U,
    const float* __restrict__ bur, const float* __restrict__ bu,
    float* __restrict__ hs)
{
    extern __shared__ __align__(16) unsigned dyn[];
    unsigned* ring = dyn;                          // 4 x 4096 words
    unsigned* sW = dyn + 16384;
    float* sP = (float*)(sW + 1024 * SPW);
    float* sBias = sP + 64 * 33;
    unsigned mb0 = (unsigned)__cvta_generic_to_shared(sBias + 32);
    unsigned ring_u32 = (unsigned)__cvta_generic_to_shared(ring);

    const int j = blockIdx.x, tid = threadIdx.x, lane = tid & 31, wid = tid >> 5;
    const int wm = wid & 3, wn = wid >> 2, q = lane >> 2, la3 = lane & 3;
    const int cown = j >> 2;

    for (int idx = tid; idx < 32 * 1024; idx += 256) {
        int n = idx & 31, k = idx >> 5;
        float v = (n < 16) ? Ur[(size_t)k * Hsz + j * 16 + n]
                           : U[(size_t)k * Hsz + j * 16 + (n - 16)];
        sW[k * SPW + (n & 7) * 4 + (n >> 3)] = f2tf(v);
    }
    if (tid < 16)      sBias[tid] = bur[j * 16 + tid];
    else if (tid < 32) sBias[tid] = bu[j * 16 + tid - 16];
    if (tid == 0) {
#pragma unroll
        for (int p = 0; p < 4; p++)
            asm volatile("mbarrier.init.shared.b64 [%0], 1;" :: "r"(mb0 + p * 8) : "memory");
        asm volatile("fence.proxy.async.shared::cta;" ::: "memory");
    }
    __syncthreads();

    const int b_e = tid >> 2, c4 = (tid & 3) * 4;
    const int bpr = (b_e & 7) * 8 + (b_e >> 3);
    const int a_col = ((q * 8 + 2 * wm) ^ (la3 << 1));
    const int bcol = q * 4 + wn * 2;
    float hh[4] = {0.f, 0.f, 0.f, 0.f};
    int ph[4] = {0, 0, 0, 0};

    for (int t = 0; t < Ssz; t++) {
        const unsigned* hsrc = g_hT[(t & 1) ^ 1];
        const unsigned tgt = 4u * (unsigned)t;
        auto poll_issue = [&](int buf, int chunk) {   // tid0 only
            unsigned v;
            do {
                asm volatile("ld.acquire.gpu.global.u32 %0, [%1];"
                             : "=r"(v) : "l"(&g_ready[chunk]) : "memory");
                if (v >= tgt) break;
                __nanosleep(20);
            } while (1);
            asm volatile("fence.proxy.async;" ::: "memory");
            asm volatile("mbarrier.arrive.expect_tx.shared.b64 _, [%0], 16384;" :: "r"(mb0 + buf * 8) : "memory");
            asm volatile("cp.async.bulk.shared::cta.global.mbarrier::complete_tx::bytes [%0], [%1], 16384, [%2];"
                         :: "r"(ring_u32 + buf * 16384), "l"(hsrc + chunk * 4096), "r"(mb0 + buf * 8) : "memory");
        };
        if (tid == 0) {
#pragma unroll
            for (int p = 0; p < 4; p++) poll_issue(p, p);
        }
        const size_t rd = (size_t)b_e * Ssz + t;
        float4 dr4 = __ldcg((const float4*)(g_Drw + rd * 2048 + j * 16 + c4));
        float4 dw4 = __ldcg((const float4*)(g_Drw + rd * 2048 + 1024 + j * 16 + c4));
        float gt = __ldcg(g_G + rd);

        float acc[2][4] = {{0.f, 0.f, 0.f, 0.f}, {0.f, 0.f, 0.f, 0.f}};
        for (int cch = 0; cch < 16; cch++) {
            const int buf = cch & 3;
            {
                unsigned mba = mb0 + buf * 8;
                unsigned par = (unsigned)ph[buf];
                asm volatile(
                    "{\n\t.reg .pred P1;\n\t"
                    "WL_%=:\n\t"
                    "mbarrier.try_wait.parity.acquire.cta.shared::cta.b64 P1, [%0], %1, 0x989680;\n\t"
                    "@P1 bra.uni WD_%=;\n\t"
                    "bra.uni WL_%=;\n\t"
                    "WD_%=:\n\t}"
                    :: "r"(mba), "r"(par) : "memory");
                ph[buf] ^= 1;
            }
            const unsigned* cb = ring + buf * 4096;
#pragma unroll
            for (int ks = 0; ks < 8; ks++) {
                int kl = ks * 8;
                uint2 A0 = *(const uint2*)&cb[(kl + la3) * 64 + a_col];
                uint2 A1 = *(const uint2*)&cb[(kl + la3 + 4) * 64 + a_col];
                unsigned a[4] = {A0.x, A0.y, A1.x, A1.y};
                int kg = cch * 64 + kl + la3;
                uint2 B0 = *(const uint2*)&sW[kg * SPW + bcol];
                uint2 B1 = *(const uint2*)&sW[(kg + 4) * SPW + bcol];
                unsigned bf0[2] = {B0.x, B1.x}, bf1[2] = {B0.y, B1.y};
                mma8(acc[0], a, bf0);
                mma8(acc[1], a, bf1);
            }
            __syncthreads();
            if (tid == 0 && cch + 4 < 16) poll_issue(cch & 3, cch + 4);
        }
        {
            int r = wm * 16 + q;
            int c0 = wn * 16 + 2 * la3, c1 = c0 + 8;
            sP[r * 33 + c0] = acc[0][0]; sP[r * 33 + c0 + 1] = acc[0][1];
            sP[(r + 8) * 33 + c0] = acc[0][2]; sP[(r + 8) * 33 + c0 + 1] = acc[0][3];
            sP[r * 33 + c1] = acc[1][0]; sP[r * 33 + c1 + 1] = acc[1][1];
            sP[(r + 8) * 33 + c1] = acc[1][2]; sP[(r + 8) * 33 + c1 + 1] = acc[1][3];
        }
        __syncthreads();
        {
            float dr[4] = {dr4.x, dr4.y, dr4.z, dr4.w};
            float dw[4] = {dw4.x, dw4.y, dw4.z, dw4.w};
            float4 ho; float* hop = &ho.x;
            unsigned* dstT = g_hT[t & 1];
#pragma unroll
            for (int i = 0; i < 4; i++) {
                int cc = c4 + i;
                float r = 1.f / (1.f + expf(-(dr[i] + sP[b_e * 33 + cc] + sBias[cc])));
                float ht = tanhf(dw[i] + r * (sP[b_e * 33 + 16 + cc] + sBias[16 + cc]));
                hh[i] = gt * ht + (1.f - gt) * hh[i];
                hop[i] = hh[i];
                dstT[(size_t)(j * 16 + cc) * 64 + (bpr ^ (i << 1))] = f2tf(hh[i]);
            }
            *(float4*)&hs[rd * Hsz + j * 16 + c4] = ho;
        }
        __syncthreads();
        if (tid == 0) {
            __threadfence();
            asm volatile("red.release.gpu.global.add.u32 [%0], %1;"
                         :: "l"(&g_ready[cown]), "r"(1u) : "memory");
        }
    }
}

// ---------------- next_mem ----------------
__global__ void __launch_bounds__(256) nextmem_kernel(
    const float* __restrict__ PM, const float* __restrict__ Q,
    const float* __restrict__ Wm, const float* __restrict__ bm,
    float* __restrict__ out, const float* __restrict__ hs)
{
    __shared__ float sW6[64 * 16];
    __shared__ float sC[64 * 65];
    const int j = blockIdx.x, tid = threadIdx.x;
    const int n = tid & 15, brow = tid >> 4;
    float acc[4] = {0.f, 0.f, 0.f, 0.f};
    for (int k0 = 0; k0 < 3072; k0 += 64) {
        sW6[tid] = Wm[(size_t)(k0 + (tid >> 4)) * Hsz + j * 16 + (tid & 15)];
        sW6[tid + 256] = Wm[(size_t)(k0 + 16 + (tid >> 4)) * Hsz + j * 16 + (tid & 15)];
        sW6[tid + 512] = Wm[(size_t)(k0 + 32 + (tid >> 4)) * Hsz + j * 16 + (tid & 15)];
        sW6[tid + 768] = Wm[(size_t)(k0 + 48 + (tid >> 4)) * Hsz + j * 16 + (tid & 15)];
#pragma unroll
        for (int it = 0; it < 16; it++) {
            int idx = tid + 256 * it;
            int b = idx >> 6, kk = idx & 63, k = k0 + kk;
            float v = (k < 1024) ? PM[b * Hsz + k]
                    : (k < 2048) ? hs[((size_t)b * Ssz + 255) * Hsz + k - 1024]
                                 : Q[b * Hsz + k - 2048];
            sC[b * 65 + kk] = v;
        }
        __syncthreads();
#pragma unroll 8
        for (int kk = 0; kk < 64; kk++) {
            float w = sW6[kk * 16 + n];
            acc[0] += sC[brow * 65 + kk] * w;
            acc[1] += sC[(brow + 16) * 65 + kk] * w;
            acc[2] += sC[(brow + 32) * 65 + kk] * w;
            acc[3] += sC[(brow + 48) * 65 + kk] * w;
        }
        __syncthreads();
    }
    float bb = bm[j * 16 + n];
    out[(size_t)brow * Hsz + j * 16 + n]        = fmaxf(acc[0] + bb, 0.f);
    out[(size_t)(brow + 16) * Hsz + j * 16 + n] = fmaxf(acc[1] + bb, 0.f);
    out[(size_t)(brow + 32) * Hsz + j * 16 + n] = fmaxf(acc[2] + bb, 0.f);
    out[(size_t)(brow + 48) * Hsz + j * 16 + n] = fmaxf(acc[3] + bb, 0.f);
}

extern "C" void kernel_launch(void* const* d_in, const int* in_sizes, int n_in,
                              void* d_out, int out_size) {
    const float* D   = (const float*)d_in[0];
    const float* Q   = (const float*)d_in[1];
    const float* PM  = (const float*)d_in[2];
    const float* Wr  = (const float*)d_in[3];
    const float* br  = (const float*)d_in[4];
    const float* Ur  = (const float*)d_in[5];
    const float* bur = (const float*)d_in[6];
    const float* Wx  = (const float*)d_in[7];
    const float* bx  = (const float*)d_in[8];
    const float* U   = (const float*)d_in[9];
    const float* bu  = (const float*)d_in[10];
    const float* W1  = (const float*)d_in[11];
    const float* b1  = (const float*)d_in[12];
    const float* W2  = (const float*)d_in[13];
    const float* Wm  = (const float*)d_in[15];
    const float* bm  = (const float*)d_in[16];
    float* out = (float*)d_out;

    static int attr_done = 0;
    if (!attr_done) {
        cudaFuncSetAttribute(scan_kernel, cudaFuncAttributeMaxDynamicSharedMemorySize, SCAN_SMEM);
        attr_done = 1;
    }

    init_kernel<<<512, 256>>>();
    gate_kernel<<<dim3(128, 8), 256>>>(D, Q, PM, W1, b1, W2);
    softmax_kernel<<<64, 256>>>();
    drw_kernel<<<dim3(128, 16), 256>>>(D, Wr, br, Wx, bx);
    scan_kernel<<<NCTA, 256, SCAN_SMEM>>>(Ur, U, bur, bu, out + Bsz * Hsz);
    nextmem_kernel<<<64, 256>>>(PM, Q, Wm, bm, out, out + Bsz * Hsz);
}

// round 10
// speedup vs baseline: 1.2933x; 1.2933x over previous
#include <cuda_runtime.h>
#include <math.h>
#include <stdint.h>

#define Bsz 64
#define Ssz 256
#define Hsz 1024
#define BS  16384
#define NCTA 64

__device__ __align__(16) float g_Drw[(size_t)BS * 2048];
__device__ __align__(16) float g_Zp[8 * BS];
__device__ __align__(16) float g_G[BS];
__device__ __align__(256) unsigned g_hT[2][Hsz * Bsz];   // [k][b'] tf32 bits, swizzled
__device__ volatile unsigned g_bar_arrive;
__device__ volatile unsigned g_bar_gen;

#define PA 20
#define PB 132
#define SPW 34

__device__ __forceinline__ unsigned f2tf(float x) {
    unsigned r; asm("cvt.rna.tf32.f32 %0, %1;" : "=r"(r) : "f"(x)); return r;
}
__device__ __forceinline__ void mma8(float* c, const unsigned* a, const unsigned* b) {
    asm volatile("mma.sync.aligned.m16n8k8.row.col.f32.tf32.tf32.f32 "
                 "{%0,%1,%2,%3},{%4,%5,%6,%7},{%8,%9},{%0,%1,%2,%3};"
                 : "+f"(c[0]), "+f"(c[1]), "+f"(c[2]), "+f"(c[3])
                 : "r"(a[0]), "r"(a[1]), "r"(a[2]), "r"(a[3]), "r"(b[0]), "r"(b[1]));
}

__device__ __forceinline__ void tile_mma(const unsigned* sA, const unsigned* sB,
                                         float c[2][8][4], int lane, int wm, int wn) {
    const int q = lane >> 2, la3 = lane & 3;
#pragma unroll
    for (int kk = 0; kk < 16; kk += 8) {
        unsigned a[2][4];
#pragma unroll
        for (int mt = 0; mt < 2; mt++) {
            int r = wm * 32 + mt * 16 + q, cc = kk + la3;
            a[mt][0] = sA[r * PA + cc];     a[mt][1] = sA[(r + 8) * PA + cc];
            a[mt][2] = sA[r * PA + cc + 4]; a[mt][3] = sA[(r + 8) * PA + cc + 4];
        }
        int kx = kk + la3, cb = q * 16 + wn * 8;
        uint4 b0 = *(const uint4*)&sB[kx * PB + cb];
        uint4 b1 = *(const uint4*)&sB[kx * PB + cb + 4];
        uint4 b2 = *(const uint4*)&sB[(kx + 4) * PB + cb];
        uint4 b3 = *(const uint4*)&sB[(kx + 4) * PB + cb + 4];
        unsigned bf[8][2] = {{b0.x,b2.x},{b0.y,b2.y},{b0.z,b2.z},{b0.w,b2.w},
                             {b1.x,b3.x},{b1.y,b3.y},{b1.z,b3.z},{b1.w,b3.w}};
#pragma unroll
        for (int mt = 0; mt < 2; mt++)
#pragma unroll
            for (int nt = 0; nt < 8; nt++) mma8(c[mt][nt], a[mt], bf[nt]);
    }
}

__global__ void init_kernel() {
    int i = blockIdx.x * blockDim.x + threadIdx.x;
    if (i == 0) { g_bar_arrive = 0; g_bar_gen = 0; }
    if (i < 2 * Bsz * Hsz) ((unsigned*)g_hT)[i] = 0u;
}

// ---------------- gate GEMM (double-buffered, verified R8) ----------------
__global__ void __launch_bounds__(256) gate_kernel(
    const float* __restrict__ D, const float* __restrict__ Q, const float* __restrict__ PM,
    const float* __restrict__ W1, const float* __restrict__ b1, const float* __restrict__ W2)
{
    __shared__ __align__(16) unsigned sA[2 * 128 * PA];
    __shared__ __align__(16) unsigned sB[2 * 16 * PB];
    __shared__ float sRed[2][128];
    const int m0 = blockIdx.x * 128, n0 = blockIdx.y * 128;
    const int tid = threadIdx.x, lane = tid & 31, wid = tid >> 5, wm = wid & 3, wn = wid >> 2;
    float c[2][8][4];
#pragma unroll
    for (int i = 0; i < 2; i++)
#pragma unroll
        for (int j = 0; j < 8; j++)
#pragma unroll
            for (int k = 0; k < 4; k++) c[i][j][k] = 0.f;
    const int am = tid >> 1, ak = (tid & 1) * 8, bk = tid >> 4;
    float ra[8], rb[8];
    auto loadAB = [&](int k0) {
        const int qd = k0 >> 10, kk = (k0 & 1023) + ak;
        const int r = m0 + am, b = r >> 8;
        const float4* dp = (const float4*)(D + (size_t)r * Hsz + kk);
        const float4* op = (const float4*)((((qd & 1) == 0) ? Q : PM) + (size_t)b * Hsz + kk);
        float4 d0 = dp[0], d1 = dp[1], o0 = op[0], o1 = op[1];
        if (qd < 2) {
            ra[0] = d0.x * o0.x; ra[1] = d0.y * o0.y; ra[2] = d0.z * o0.z; ra[3] = d0.w * o0.w;
            ra[4] = d1.x * o1.x; ra[5] = d1.y * o1.y; ra[6] = d1.z * o1.z; ra[7] = d1.w * o1.w;
        } else {
            ra[0] = fabsf(d0.x - o0.x); ra[1] = fabsf(d0.y - o0.y); ra[2] = fabsf(d0.z - o0.z); ra[3] = fabsf(d0.w - o0.w);
            ra[4] = fabsf(d1.x - o1.x); ra[5] = fabsf(d1.y - o1.y); ra[6] = fabsf(d1.z - o1.z); ra[7] = fabsf(d1.w - o1.w);
        }
        const float4* wp = (const float4*)(W1 + (size_t)(k0 + bk) * Hsz + n0 + (tid & 15) * 8);
        float4 w0 = wp[0], w1 = wp[1];
        rb[0] = w0.x; rb[1] = w0.y; rb[2] = w0.z; rb[3] = w0.w;
        rb[4] = w1.x; rb[5] = w1.y; rb[6] = w1.z; rb[7] = w1.w;
    };
    auto storeAB = [&](int bsel) {
        unsigned* pA = sA + bsel * 128 * PA;
        unsigned* pB = sB + bsel * 16 * PB;
#pragma unroll
        for (int i = 0; i < 8; i++) pA[am * PA + ak + i] = f2tf(ra[i]);
#pragma unroll
        for (int i = 0; i < 8; i++) pB[bk * PB + i * 16 + (tid & 15)] = f2tf(rb[i]);
    };
    loadAB(0); storeAB(0); __syncthreads();
    int cur = 0;
    for (int k0 = 0; k0 < 4096; k0 += 16) {
        const bool more = (k0 + 16) < 4096;
        if (more) loadAB(k0 + 16);
        tile_mma(sA + cur * 128 * PA, sB + cur * 16 * PB, c, lane, wm, wn);
        if (more) storeAB(cur ^ 1);
        __syncthreads();
        cur ^= 1;
    }
#pragma unroll
    for (int mt = 0; mt < 2; mt++) {
        float s0 = 0.f, s1 = 0.f;
#pragma unroll
        for (int nt = 0; nt < 8; nt++) {
            int nc = n0 + wn * 64 + nt * 8 + (lane & 3) * 2;
            float bb0 = b1[nc], bb1 = b1[nc + 1];
            float w0 = W2[nc], w1 = W2[nc + 1];
            s0 += tanhf(c[mt][nt][0] + bb0) * w0 + tanhf(c[mt][nt][1] + bb1) * w1;
            s1 += tanhf(c[mt][nt][2] + bb0) * w0 + tanhf(c[mt][nt][3] + bb1) * w1;
        }
        s0 += __shfl_xor_sync(0xffffffffu, s0, 1); s0 += __shfl_xor_sync(0xffffffffu, s0, 2);
        s1 += __shfl_xor_sync(0xffffffffu, s1, 1); s1 += __shfl_xor_sync(0xffffffffu, s1, 2);
        if ((lane & 3) == 0) {
            int rl = wm * 32 + mt * 16 + (lane >> 2);
            sRed[wn][rl] = s0; sRed[wn][rl + 8] = s1;
        }
    }
    __syncthreads();
    if (tid < 128) g_Zp[blockIdx.y * BS + m0 + tid] = sRed[0][tid] + sRed[1][tid];
}

__global__ void __launch_bounds__(256) softmax_kernel() {
    __shared__ float red[256];
    const int b = blockIdx.x, s = threadIdx.x;
    float v = 0.f;
#pragma unroll
    for (int p = 0; p < 8; p++) v += g_Zp[p * BS + b * Ssz + s];
    red[s] = v; __syncthreads();
    for (int o = 128; o > 0; o >>= 1) { if (s < o) red[s] = fmaxf(red[s], red[s + o]); __syncthreads(); }
    float mx = red[0]; __syncthreads();
    float e = expf(v - mx);
    red[s] = e; __syncthreads();
    for (int o = 128; o > 0; o >>= 1) { if (s < o) red[s] += red[s + o]; __syncthreads(); }
    g_G[b * Ssz + s] = e / red[0];
}

// ---------------- Dr|Dw (double-buffered, verified R8) ----------------
__global__ void __launch_bounds__(256) drw_kernel(
    const float* __restrict__ D, const float* __restrict__ Wr, const float* __restrict__ br,
    const float* __restrict__ Wx, const float* __restrict__ bx)
{
    __shared__ __align__(16) unsigned sA[2 * 128 * PA];
    __shared__ __align__(16) unsigned sB[2 * 16 * PB];
    const int m0 = blockIdx.x * 128, n0g = blockIdx.y * 128;
    const float* W = (n0g < 1024) ? Wr : Wx;
    const float* bias = (n0g < 1024) ? br : bx;
    const int n0 = n0g & 1023;
    const int tid = threadIdx.x, lane = tid & 31, wid = tid >> 5, wm = wid & 3, wn = wid >> 2;
    float c[2][8][4];
#pragma unroll
    for (int i = 0; i < 2; i++)
#pragma unroll
        for (int j = 0; j < 8; j++)
#pragma unroll
            for (int k = 0; k < 4; k++) c[i][j][k] = 0.f;
    const int am = tid >> 1, ak = (tid & 1) * 8, bk = tid >> 4;
    float ra[8], rb[8];
    auto loadAB = [&](int k0) {
        const float4* dp = (const float4*)(D + (size_t)(m0 + am) * Hsz + k0 + ak);
        float4 d0 = dp[0], d1 = dp[1];
        ra[0] = d0.x; ra[1] = d0.y; ra[2] = d0.z; ra[3] = d0.w;
        ra[4] = d1.x; ra[5] = d1.y; ra[6] = d1.z; ra[7] = d1.w;
        const float4* wp = (const float4*)(W + (size_t)(k0 + bk) * Hsz + n0 + (tid & 15) * 8);
        float4 w0 = wp[0], w1 = wp[1];
        rb[0] = w0.x; rb[1] = w0.y; rb[2] = w0.z; rb[3] = w0.w;
        rb[4] = w1.x; rb[5] = w1.y; rb[6] = w1.z; rb[7] = w1.w;
    };
    auto storeAB = [&](int bsel) {
        unsigned* pA = sA + bsel * 128 * PA;
        unsigned* pB = sB + bsel * 16 * PB;
#pragma unroll
        for (int i = 0; i < 8; i++) pA[am * PA + ak + i] = f2tf(ra[i]);
#pragma unroll
        for (int i = 0; i < 8; i++) pB[bk * PB + i * 16 + (tid & 15)] = f2tf(rb[i]);
    };
    loadAB(0); storeAB(0); __syncthreads();
    int cur = 0;
    for (int k0 = 0; k0 < 1024; k0 += 16) {
        const bool more = (k0 + 16) < 1024;
        if (more) loadAB(k0 + 16);
        tile_mma(sA + cur * 128 * PA, sB + cur * 16 * PB, c, lane, wm, wn);
        if (more) storeAB(cur ^ 1);
        __syncthreads();
        cur ^= 1;
    }
#pragma unroll
    for (int mt = 0; mt < 2; mt++)
#pragma unroll
        for (int nt = 0; nt < 8; nt++) {
            int nl = wn * 64 + nt * 8 + (lane & 3) * 2;
            int r0 = m0 + wm * 32 + mt * 16 + (lane >> 2);
            float bb0 = bias[n0 + nl], bb1 = bias[n0 + nl + 1];
            *(float2*)&g_Drw[(size_t)r0 * 2048 + n0g + nl] = make_float2(c[mt][nt][0] + bb0, c[mt][nt][1] + bb1);
            *(float2*)&g_Drw[(size_t)(r0 + 8) * 2048 + n0g + nl] = make_float2(c[mt][nt][2] + bb0, c[mt][nt][3] + bb1);
        }
}

// ---------------- persistent scan: 512 threads, 2-way K-split ----------------
// words: ring 4x4096 | sW 1024*SPW | sP0 2112 | sP1 2112 | bias 32 | mbar 8
#define R_RING 0
#define R_SW   16384
#define R_SP0  (R_SW + 1024 * SPW)
#define R_SP1  (R_SP0 + 64 * 33)
#define R_BIAS (R_SP1 + 64 * 33)
#define R_MB   (R_BIAS + 32)
#define SCAN_WORDS (R_MB + 8)
#define SCAN_SMEM  (SCAN_WORDS * 4 + 1024)

__device__ __forceinline__ void wait_par(unsigned mba, unsigned par) {
    asm volatile("{\n\t.reg .pred P1;\n\tWL_%=:\n\t"
        "mbarrier.try_wait.parity.acquire.cta.shared::cta.b64 P1, [%0], %1, 0x989680;\n\t"
        "@P1 bra.uni WD_%=;\n\tbra.uni WL_%=;\n\tWD_%=:\n\t}"
        :: "r"(mba), "r"(par) : "memory");
}

__device__ __forceinline__ void gbar512() {
    __syncthreads();
    if (threadIdx.x == 0) {
        __threadfence();
        unsigned gen = g_bar_gen;
        if (atomicAdd((unsigned*)&g_bar_arrive, 1u) == NCTA - 1) {
            g_bar_arrive = 0;
            __threadfence();
            g_bar_gen = gen + 1;
        } else {
            while (g_bar_gen == gen) __nanosleep(32);
            __threadfence();
        }
    }
    __syncthreads();
}

__global__ void __launch_bounds__(512, 1) scan_kernel(
    const float* __restrict__ Ur, const float* __restrict__ U,
    const float* __restrict__ bur, const float* __restrict__ bu,
    float* __restrict__ hs)
{
    extern __shared__ __align__(16) unsigned dynraw[];
    unsigned* dyn = (unsigned*)(((uintptr_t)dynraw + 1023) & ~(uintptr_t)1023);
    unsigned* ring = dyn + R_RING;
    unsigned* sW = dyn + R_SW;
    float* sP0 = (float*)(dyn + R_SP0);
    float* sP1 = (float*)(dyn + R_SP1);
    float* sBias = (float*)(dyn + R_BIAS);
    unsigned mb0 = (unsigned)__cvta_generic_to_shared(dyn + R_MB);   // [g*2+b]*8
    unsigned ring_u32 = (unsigned)__cvta_generic_to_shared(ring);

    const int j = blockIdx.x, tid = threadIdx.x, lane = tid & 31, wid = tid >> 5;
    const int grp = wid >> 3, wg = wid & 7;                 // group, warp-in-group
    const int wm = wg & 3, wn = wg >> 2, q = lane >> 2, la3 = lane & 3;
    float* sPg = grp ? sP1 : sP0;

    for (int idx = tid; idx < 32 * 1024; idx += 512) {
        int n = idx & 31, k = idx >> 5;
        float v = (n < 16) ? Ur[(size_t)k * Hsz + j * 16 + n]
                           : U[(size_t)k * Hsz + j * 16 + (n - 16)];
        sW[k * SPW + (n & 7) * 4 + (n >> 3)] = f2tf(v);
    }
    if (tid < 16)      sBias[tid] = bur[j * 16 + tid];
    else if (tid < 32) sBias[tid] = bu[j * 16 + tid - 16];
    if (tid == 0) {
#pragma unroll
        for (int p = 0; p < 4; p++)
            asm volatile("mbarrier.init.shared.b64 [%0], 1;" :: "r"(mb0 + p * 8) : "memory");
        asm volatile("fence.proxy.async.shared::cta;" ::: "memory");
    }
    __syncthreads();

    const int b_e = tid >> 2, c4 = (tid & 3) * 4;           // epilogue: tid<256
    const int bpr = (b_e & 7) * 8 + (b_e >> 3);
    const int a_col = ((q * 8 + 2 * wm) ^ (la3 << 1));
    const int bcol = q * 4 + wn * 2;
    float hh[4] = {0.f, 0.f, 0.f, 0.f};
    unsigned cntF[2] = {0, 0};
    const bool isprod = (tid == 0) || (tid == 256);

    for (int t = 0; t < Ssz; t++) {
        const unsigned* hsrc = g_hT[(t & 1) ^ 1];
        // producer: issue chunks 0,1 of this group's stream
        if (isprod) {
#pragma unroll
            for (int cl = 0; cl < 2; cl++) {
                unsigned mba = mb0 + (grp * 2 + cl) * 8;
                asm volatile("mbarrier.arrive.expect_tx.shared.b64 _, [%0], 16384;" :: "r"(mba) : "memory");
                asm volatile("cp.async.bulk.shared::cta.global.mbarrier::complete_tx::bytes [%0], [%1], 16384, [%2];"
                             :: "r"(ring_u32 + (grp * 2 + cl) * 16384),
                                "l"(hsrc + (grp * 512 + cl * 64) * 64),
                                "r"(mb0 + (grp * 2 + cl) * 8) : "memory");
            }
        }
        float4 dr4, dw4; float gt = 0.f;
        if (tid < 256) {
            const size_t rd = (size_t)b_e * Ssz + t;
            dr4 = __ldcg((const float4*)(g_Drw + rd * 2048 + j * 16 + c4));
            dw4 = __ldcg((const float4*)(g_Drw + rd * 2048 + 1024 + j * 16 + c4));
            gt = __ldcg(g_G + rd);
        }
        float acc[2][4] = {{0.f, 0.f, 0.f, 0.f}, {0.f, 0.f, 0.f, 0.f}};
        for (int cl = 0; cl < 8; cl++) {
            const int buf = cl & 1;
            wait_par(mb0 + (grp * 2 + buf) * 8, cntF[buf] & 1);
            cntF[buf]++;
            const unsigned* cb = ring + (grp * 2 + buf) * 4096;
#pragma unroll
            for (int ks = 0; ks < 8; ks++) {
                int kl = ks * 8;
                uint2 A0 = *(const uint2*)&cb[(kl + la3) * 64 + a_col];
                uint2 A1 = *(const uint2*)&cb[(kl + la3 + 4) * 64 + a_col];
                unsigned a[4] = {A0.x, A0.y, A1.x, A1.y};
                int kg = grp * 512 + cl * 64 + kl + la3;
                uint2 B0 = *(const uint2*)&sW[kg * SPW + bcol];
                uint2 B1 = *(const uint2*)&sW[(kg + 4) * SPW + bcol];
                unsigned bf0[2] = {B0.x, B1.x}, bf1[2] = {B0.y, B1.y};
                mma8(acc[0], a, bf0);
                mma8(acc[1], a, bf1);
            }
            // group barrier: buffer fully consumed by this group's 8 warps
            asm volatile("bar.sync %0, 256;" :: "r"(grp + 1) : "memory");
            if (isprod && cl + 2 < 8) {
                unsigned mba = mb0 + (grp * 2 + buf) * 8;
                asm volatile("mbarrier.arrive.expect_tx.shared.b64 _, [%0], 16384;" :: "r"(mba) : "memory");
                asm volatile("cp.async.bulk.shared::cta.global.mbarrier::complete_tx::bytes [%0], [%1], 16384, [%2];"
                             :: "r"(ring_u32 + (grp * 2 + buf) * 16384),
                                "l"(hsrc + (grp * 512 + (cl + 2) * 64) * 64),
                                "r"(mba) : "memory");
            }
        }
        {
            int r = wm * 16 + q;
            int c0 = wn * 16 + 2 * la3, c1 = c0 + 8;
            sPg[r * 33 + c0] = acc[0][0]; sPg[r * 33 + c0 + 1] = acc[0][1];
            sPg[(r + 8) * 33 + c0] = acc[0][2]; sPg[(r + 8) * 33 + c0 + 1] = acc[0][3];
            sPg[r * 33 + c1] = acc[1][0]; sPg[r * 33 + c1 + 1] = acc[1][1];
            sPg[(r + 8) * 33 + c1] = acc[1][2]; sPg[(r + 8) * 33 + c1 + 1] = acc[1][3];
        }
        __syncthreads();
        if (tid < 256) {
            const size_t rd = (size_t)b_e * Ssz + t;
            float dr[4] = {dr4.x, dr4.y, dr4.z, dr4.w};
            float dw[4] = {dw4.x, dw4.y, dw4.z, dw4.w};
            float4 ho; float* hop = &ho.x;
            uint4 hb; unsigned* hbp = &hb.x;
            unsigned* dstT = g_hT[t & 1];
#pragma unroll
            for (int i = 0; i < 4; i++) {
                int cc = c4 + i;
                float pr = sP0[b_e * 33 + cc] + sP1[b_e * 33 + cc];
                float pu = sP0[b_e * 33 + 16 + cc] + sP1[b_e * 33 + 16 + cc];
                float r = 1.f / (1.f + expf(-(dr[i] + pr + sBias[cc])));
                float ht = tanhf(dw[i] + r * (pu + sBias[16 + cc]));
                hh[i] = gt * ht + (1.f - gt) * hh[i];
                hop[i] = hh[i];
                hbp[i] = f2tf(hh[i]);
            }
            *(float4*)&hs[rd * Hsz + j * 16 + c4] = ho;
            dstT[(size_t)(j * 16 + c4) * 64 + (bpr ^ 0)] = hb.x;
            dstT[(size_t)(j * 16 + c4 + 1) * 64 + (bpr ^ 2)] = hb.y;
            dstT[(size_t)(j * 16 + c4 + 2) * 64 + (bpr ^ 4)] = hb.z;
            dstT[(size_t)(j * 16 + c4 + 3) * 64 + (bpr ^ 6)] = hb.w;
        }
        gbar512();
    }
}

// ---------------- next_mem ----------------
__global__ void __launch_bounds__(256) nextmem_kernel(
    const float* __restrict__ PM, const float* __restrict__ Q,
    const float* __restrict__ Wm, const float* __restrict__ bm,
    float* __restrict__ out, const float* __restrict__ hs)
{
    __shared__ float sW6[64 * 16];
    __shared__ float sC[64 * 65];
    const int j = blockIdx.x, tid = threadIdx.x;
    const int n = tid & 15, brow = tid >> 4;
    float acc[4] = {0.f, 0.f, 0.f, 0.f};
    for (int k0 = 0; k0 < 3072; k0 += 64) {
        sW6[tid] = Wm[(size_t)(k0 + (tid >> 4)) * Hsz + j * 16 + (tid & 15)];
        sW6[tid + 256] = Wm[(size_t)(k0 + 16 + (tid >> 4)) * Hsz + j * 16 + (tid & 15)];
        sW6[tid + 512] = Wm[(size_t)(k0 + 32 + (tid >> 4)) * Hsz + j * 16 + (tid & 15)];
        sW6[tid + 768] = Wm[(size_t)(k0 + 48 + (tid >> 4)) * Hsz + j * 16 + (tid & 15)];
#pragma unroll
        for (int it = 0; it < 16; it++) {
            int idx = tid + 256 * it;
            int b = idx >> 6, kk = idx & 63, k = k0 + kk;
            float v = (k < 1024) ? PM[b * Hsz + k]
                    : (k < 2048) ? hs[((size_t)b * Ssz + 255) * Hsz + k - 1024]
                                 : Q[b * Hsz + k - 2048];
            sC[b * 65 + kk] = v;
        }
        __syncthreads();
#pragma unroll 8
        for (int kk = 0; kk < 64; kk++) {
            float w = sW6[kk * 16 + n];
            acc[0] += sC[brow * 65 + kk] * w;
            acc[1] += sC[(brow + 16) * 65 + kk] * w;
            acc[2] += sC[(brow + 32) * 65 + kk] * w;
            acc[3] += sC[(brow + 48) * 65 + kk] * w;
        }
        __syncthreads();
    }
    float bb = bm[j * 16 + n];
    out[(size_t)brow * Hsz + j * 16 + n]        = fmaxf(acc[0] + bb, 0.f);
    out[(size_t)(brow + 16) * Hsz + j * 16 + n] = fmaxf(acc[1] + bb, 0.f);
    out[(size_t)(brow + 32) * Hsz + j * 16 + n] = fmaxf(acc[2] + bb, 0.f);
    out[(size_t)(brow + 48) * Hsz + j * 16 + n] = fmaxf(acc[3] + bb, 0.f);
}

extern "C" void kernel_launch(void* const* d_in, const int* in_sizes, int n_in,
                              void* d_out, int out_size) {
    const float* D   = (const float*)d_in[0];
    const float* Q   = (const float*)d_in[1];
    const float* PM  = (const float*)d_in[2];
    const float* Wr  = (const float*)d_in[3];
    const float* br  = (const float*)d_in[4];
    const float* Ur  = (const float*)d_in[5];
    const float* bur = (const float*)d_in[6];
    const float* Wx  = (const float*)d_in[7];
    const float* bx  = (const float*)d_in[8];
    const float* U   = (const float*)d_in[9];
    const float* bu  = (const float*)d_in[10];
    const float* W1  = (const float*)d_in[11];
    const float* b1  = (const float*)d_in[12];
    const float* W2  = (const float*)d_in[13];
    const float* Wm  = (const float*)d_in[15];
    const float* bm  = (const float*)d_in[16];
    float* out = (float*)d_out;

    static int attr_done = 0;
    if (!attr_done) {
        cudaFuncSetAttribute(scan_kernel, cudaFuncAttributeMaxDynamicSharedMemorySize, SCAN_SMEM);
        attr_done = 1;
    }

    init_kernel<<<512, 256>>>();
    gate_kernel<<<dim3(128, 8), 256>>>(D, Q, PM, W1, b1, W2);
    softmax_kernel<<<64, 256>>>();
    drw_kernel<<<dim3(128, 16), 256>>>(D, Wr, br, Wx, bx);
    scan_kernel<<<NCTA, 512, SCAN_SMEM>>>(Ur, U, bur, bu, out + Bsz * Hsz);
    nextmem_kernel<<<64, 256>>>(PM, Q, Wm, bm, out, out + Bsz * Hsz);
}